// round 2
// baseline (speedup 1.0000x reference)
#include <cuda_runtime.h>

// Problem shape (fixed by the reference)
#define S 32768
#define H 1024
#define HF4 (H / 4)      // 256 float4 per row
#define B1 296           // stage-1 blocks (2 per SM on 148 SMs)
#define TPB 256
#define WPB 8            // warps per block

// Deterministic cross-block reduction scratch (module-load allocated, not runtime alloc)
__device__ float g_partial[B1 * H];

__global__ __launch_bounds__(TPB, 2)
void cosattn_stage1(const float* __restrict__ query,
                    const float* __restrict__ keys) {
    __shared__ float warp_ctx[WPB][H];   // 32 KB

    const int tid  = threadIdx.x;
    const int wid  = tid >> 5;
    const int lane = tid & 31;
    const int gwarp  = blockIdx.x * WPB + wid;
    const int nwarps = gridDim.x * WPB;

    // Each lane owns float4 columns {lane + 32*j}, j=0..7 -> warp covers all 1024 cols.
    const float4* q4 = (const float4*)query;
    float4 qv[8];
    float qss = 0.f;
#pragma unroll
    for (int j = 0; j < 8; j++) {
        qv[j] = q4[lane + 32 * j];
        qss += qv[j].x * qv[j].x + qv[j].y * qv[j].y
             + qv[j].z * qv[j].z + qv[j].w * qv[j].w;
    }
#pragma unroll
    for (int o = 16; o > 0; o >>= 1)
        qss += __shfl_xor_sync(0xffffffffu, qss, o);
    const float qn_inv = rsqrtf(qss);

    float4 acc[8];
#pragma unroll
    for (int j = 0; j < 8; j++) acc[j] = make_float4(0.f, 0.f, 0.f, 0.f);

    for (int row = gwarp; row < S; row += nwarps) {
        const float4* k4 = (const float4*)(keys + (size_t)row * H);
        float4 kv[8];
#pragma unroll
        for (int j = 0; j < 8; j++) kv[j] = k4[lane + 32 * j];

        float dot = 0.f, ss = 0.f;
#pragma unroll
        for (int j = 0; j < 8; j++) {
            dot += qv[j].x * kv[j].x + qv[j].y * kv[j].y
                 + qv[j].z * kv[j].z + qv[j].w * kv[j].w;
            ss  += kv[j].x * kv[j].x + kv[j].y * kv[j].y
                 + kv[j].z * kv[j].z + kv[j].w * kv[j].w;
        }
#pragma unroll
        for (int o = 16; o > 0; o >>= 1) {
            dot += __shfl_xor_sync(0xffffffffu, dot, o);
            ss  += __shfl_xor_sync(0xffffffffu, ss, o);
        }
        const float cosv = dot * qn_inv * rsqrtf(ss);

#pragma unroll
        for (int j = 0; j < 8; j++) {
            acc[j].x += cosv * kv[j].x;
            acc[j].y += cosv * kv[j].y;
            acc[j].z += cosv * kv[j].z;
            acc[j].w += cosv * kv[j].w;
        }
    }

    // Per-warp slice to shared (conflict-free LDS/STS.128), then block tree-reduce.
    float4* wctx4 = (float4*)warp_ctx[wid];
#pragma unroll
    for (int j = 0; j < 8; j++) wctx4[lane + 32 * j] = acc[j];
    __syncthreads();

    // Thread tid reduces float4-column tid across the 8 warp slices.
    float4 sum = make_float4(0.f, 0.f, 0.f, 0.f);
#pragma unroll
    for (int w = 0; w < WPB; w++) {
        float4 v = ((const float4*)warp_ctx[w])[tid];
        sum.x += v.x; sum.y += v.y; sum.z += v.z; sum.w += v.w;
    }
    ((float4*)(g_partial + (size_t)blockIdx.x * H))[tid] = sum;
}

// Stage 2: deterministically reduce B1 partials per column, write d_out.
// 64 blocks x 256 threads; block handles 16 columns, 16 w-slices per column.
__global__ void cosattn_stage2(float* __restrict__ out) {
    __shared__ float red[256];
    const int tid      = threadIdx.x;
    const int colLocal = tid & 15;
    const int wslice   = tid >> 4;
    const int col      = blockIdx.x * 16 + colLocal;

    float s = 0.f;
    for (int w = wslice; w < B1; w += 16)
        s += g_partial[w * H + col];
    red[tid] = s;
    __syncthreads();

    if (tid < 16) {
        float t = 0.f;
#pragma unroll
        for (int k = 0; k < 16; k++) t += red[k * 16 + tid];
        out[blockIdx.x * 16 + tid] = t;
    }
}

extern "C" void kernel_launch(void* const* d_in, const int* in_sizes, int n_in,
                              void* d_out, int out_size) {
    const float* query = (const float*)d_in[0];  // [1, 1024]
    const float* keys  = (const float*)d_in[1];  // [32768, 1024]
    float* out = (float*)d_out;                  // [1, 1024]

    cosattn_stage1<<<B1, TPB>>>(query, keys);
    cosattn_stage2<<<H / 16, 256>>>(out);
}

// round 3
// speedup vs baseline: 1.0906x; 1.0906x over previous
#include <cuda_runtime.h>

// Problem shape (fixed by the reference)
#define S 32768
#define H 1024
#define B1 296           // blocks = 2 per SM on 148 SMs (all co-resident -> grid barrier safe)
#define TPB 256
#define WPB 8            // warps per block
#define NF4 (H / 4)      // 256 float4 columns

// Transposed partial layout: g_part[f4col][block] (float4 each) -> contiguous per column.
__device__ float4 g_part[NF4][B1];
// Monotone arrival counter (zero-initialized at module load; epoch trick => no reset needed).
__device__ unsigned int g_cnt;

__global__ __launch_bounds__(TPB, 2)
void cosattn_fused(const float* __restrict__ query,
                   const float* __restrict__ keys,
                   float* __restrict__ out) {
    __shared__ float warp_ctx[WPB][H];   // 32 KB (reused as reduce buffer in phase 2)

    const int tid  = threadIdx.x;
    const int wid  = tid >> 5;
    const int lane = tid & 31;
    const int gwarp  = blockIdx.x * WPB + wid;
    const int nwarps = gridDim.x * WPB;

    // ---------------- Phase 1: fused cosine-weighted accumulation ----------------
    // Lane owns float4 columns {lane + 32*j}, j=0..7 -> warp covers all 1024 cols.
    const float4* q4 = (const float4*)query;
    float4 qv[8];
    float qss = 0.f;
#pragma unroll
    for (int j = 0; j < 8; j++) {
        qv[j] = q4[lane + 32 * j];
        qss += qv[j].x * qv[j].x + qv[j].y * qv[j].y
             + qv[j].z * qv[j].z + qv[j].w * qv[j].w;
    }
#pragma unroll
    for (int o = 16; o > 0; o >>= 1)
        qss += __shfl_xor_sync(0xffffffffu, qss, o);
    const float qn_inv = rsqrtf(qss);

    float4 acc[8];
#pragma unroll
    for (int j = 0; j < 8; j++) acc[j] = make_float4(0.f, 0.f, 0.f, 0.f);

    for (int row = gwarp; row < S; row += nwarps) {
        const float4* k4 = (const float4*)(keys + (size_t)row * H);
        float4 kv[8];
#pragma unroll
        for (int j = 0; j < 8; j++) kv[j] = k4[lane + 32 * j];

        float dot = 0.f, ss = 0.f;
#pragma unroll
        for (int j = 0; j < 8; j++) {
            dot += qv[j].x * kv[j].x + qv[j].y * kv[j].y
                 + qv[j].z * kv[j].z + qv[j].w * kv[j].w;
            ss  += kv[j].x * kv[j].x + kv[j].y * kv[j].y
                 + kv[j].z * kv[j].z + kv[j].w * kv[j].w;
        }
#pragma unroll
        for (int o = 16; o > 0; o >>= 1) {
            dot += __shfl_xor_sync(0xffffffffu, dot, o);
            ss  += __shfl_xor_sync(0xffffffffu, ss, o);
        }
        const float cosv = dot * qn_inv * rsqrtf(ss);

#pragma unroll
        for (int j = 0; j < 8; j++) {
            acc[j].x += cosv * kv[j].x;
            acc[j].y += cosv * kv[j].y;
            acc[j].z += cosv * kv[j].z;
            acc[j].w += cosv * kv[j].w;
        }
    }

    // Block-level reduce: per-warp slice to shared, then thread tid sums its float4 column.
    float4* wctx4 = (float4*)warp_ctx[wid];
#pragma unroll
    for (int j = 0; j < 8; j++) wctx4[lane + 32 * j] = acc[j];
    __syncthreads();

    float4 sum = make_float4(0.f, 0.f, 0.f, 0.f);
#pragma unroll
    for (int w = 0; w < WPB; w++) {
        float4 v = ((const float4*)warp_ctx[w])[tid];
        sum.x += v.x; sum.y += v.y; sum.z += v.z; sum.w += v.w;
    }
    // Transposed store: column tid, row blockIdx.x (scattered but tiny: 256 stores/block).
    g_part[tid][blockIdx.x] = sum;

    // ---------------- Grid barrier (all 296 blocks co-resident) ----------------
    __threadfence();            // release: make this thread's g_part stores visible
    __syncthreads();
    __shared__ unsigned int s_target;
    if (tid == 0) {
        unsigned int old = atomicAdd(&g_cnt, 1u);
        unsigned int target = old - (old % B1) + B1;   // next multiple of B1 (epoch-safe)
        while (*(volatile unsigned int*)&g_cnt < target)
            __nanosleep(64);
        s_target = target;      // also serves as the spin result handoff
    }
    __syncthreads();
    __threadfence();            // acquire: see all blocks' g_part stores
    (void)s_target;

    // ---------------- Phase 2: cross-block reduction, fully parallel ----------------
    // Block b < 256 reduces float4-column b: 296 contiguous float4 in L2.
    const int b = blockIdx.x;
    if (b < NF4) {
        float4 a = make_float4(0.f, 0.f, 0.f, 0.f);
        for (int r = tid; r < B1; r += TPB) {          // coalesced: consecutive tid -> consecutive float4
            float4 v = g_part[b][r];
            a.x += v.x; a.y += v.y; a.z += v.z; a.w += v.w;
        }
        float4* red = (float4*)warp_ctx[0];            // reuse smem (4 KB)
        red[tid] = a;
        __syncthreads();
#pragma unroll
        for (int s = TPB / 2; s > 0; s >>= 1) {
            if (tid < s) {
                float4 o = red[tid + s];
                red[tid].x += o.x; red[tid].y += o.y;
                red[tid].z += o.z; red[tid].w += o.w;
            }
            __syncthreads();
        }
        if (tid == 0)
            ((float4*)out)[b] = red[0];
    }
}

extern "C" void kernel_launch(void* const* d_in, const int* in_sizes, int n_in,
                              void* d_out, int out_size) {
    const float* query = (const float*)d_in[0];  // [1, 1024]
    const float* keys  = (const float*)d_in[1];  // [32768, 1024]
    float* out = (float*)d_out;                  // [1, 1024]

    cosattn_fused<<<B1, TPB>>>(query, keys, out);
}